// round 12
// baseline (speedup 1.0000x reference)
#include <cuda_runtime.h>
#include <cstdint>

// ALIF forward scan — quad-buffered register pipeline + L2 prefetch front.
// x_seq: [T, n_flat] fp32; state v, a: [n_flat]; out spikes [T, n_flat] fp32.
// Per step: v = dv*v + x; th = th0 + beta*a; s = (v>th); v -= s*th; a = da*a + s.
//
// Thread-per-neuron, sequential T. Demand loads run through a 4-phase register
// pipeline (consume 3 batches after issue). A prefetch front runs 64 steps
// ahead: lane l prefetches step t+64+(l&7), so lanes {k,k+8,k+16,k+24} cover
// the 4 sectors of step-k's 128B line — one prefetch instruction per 8-step
// batch pulls all 8 future lines into L2. Demand loads then hit L2 (~250cyc),
// fully covered by the register lookahead; the DRAM read stream is driven by
// the prefetch front, decoupled from the serial recurrence.

#define U 8       // timesteps per batch
#define PD 8      // prefetch distance in batches (64 steps)
#define BLKN 64   // threads per CTA

__device__ __forceinline__ float alif_step(float& v, float& a, float xv,
                                           float dv, float da, float th0, float beta) {
    v = fmaf(dv, v, xv);
    float th = fmaf(beta, a, th0);
    float s = (v > th) ? 1.0f : 0.0f;
    v = fmaf(-s, th, v);
    a = fmaf(da, a, s);
    return s;
}

__global__ __launch_bounds__(BLKN)
void ALIF_24309514895931_kernel(const float* __restrict__ x,
                                const float* __restrict__ v0,
                                const float* __restrict__ a0,
                                const float* __restrict__ dv_p,
                                const float* __restrict__ da_p,
                                const float* __restrict__ th_p,
                                const float* __restrict__ beta_p,
                                float* __restrict__ out,
                                int n_flat, int T) {
    int tid = threadIdx.x;
    int i = blockIdx.x * BLKN + tid;
    if (i >= n_flat) return;

    const float dv   = *dv_p;
    const float da   = *da_p;
    const float th0  = *th_p;
    const float beta = *beta_p;

    float v = v0[i];
    float a = a0[i];

    const float* xp = x + i;
    float* op = out + i;
    const unsigned int stride = (unsigned int)n_flat;
    const int lane8 = tid & 7;

    const int nb = T / U;

    float b0[U], b1[U], b2[U], b3[U];

    // One instruction prefetches the 8 lines (all sectors) of batch (bi+PD).
#define PREF(bi)                                                            \
    {                                                                       \
        int pstep = ((bi) + PD) * U + lane8;                                \
        if (pstep > T - 1) pstep = T - 1;                                   \
        asm volatile("prefetch.global.L2 [%0];"                             \
                     :: "l"(xp + (size_t)pstep * stride));                  \
    }

#define LOADBLK(buf, bi)                                                    \
    {                                                                       \
        PREF(bi);                                                           \
        unsigned int base = (unsigned int)(bi) * U * stride;                \
        _Pragma("unroll")                                                   \
        for (int k = 0; k < U; k++)                                         \
            (buf)[k] = __ldcs(xp + base + (unsigned int)k * stride);        \
    }

#define COMPBLK(buf, bi)                                                    \
    {                                                                       \
        unsigned int base = (unsigned int)(bi) * U * stride;                \
        _Pragma("unroll")                                                   \
        for (int k = 0; k < U; k++) {                                       \
            float s = alif_step(v, a, (buf)[k], dv, da, th0, beta);         \
            __stcs(op + base + (unsigned int)k * stride, s);                \
        }                                                                   \
    }

    if (nb >= 4) {
        // Prologue: batches 0,1,2 in flight (each also prefetches +PD).
        LOADBLK(b0, 0);
        LOADBLK(b1, 1);
        LOADBLK(b2, 2);

        int g = 0;
        // Main 4-phase rotation: load g+3+p while computing g+p.
        for (; g + 4 <= nb; g += 4) {
            if (g + 3 < nb) LOADBLK(b3, g + 3);
            COMPBLK(b0, g);
            if (g + 4 < nb) LOADBLK(b0, g + 4);
            COMPBLK(b1, g + 1);
            if (g + 5 < nb) LOADBLK(b1, g + 5);
            COMPBLK(b2, g + 2);
            if (g + 6 < nb) LOADBLK(b2, g + 6);
            COMPBLK(b3, g + 3);
        }
        // Remainder batches (<4): already loaded by the guarded loads above.
        int r = nb - g;
        if (r > 0) COMPBLK(b0, g);
        if (r > 1) COMPBLK(b1, g + 1);
        if (r > 2) COMPBLK(b2, g + 2);
    } else {
        for (int b = 0; b < nb; b++) {
            LOADBLK(b0, b);
            COMPBLK(b0, b);
        }
    }

    // Tail (T not a multiple of U).
    for (int t = nb * U; t < T; t++) {
        float xv = __ldcs(xp + (unsigned int)t * stride);
        float s = alif_step(v, a, xv, dv, da, th0, beta);
        __stcs(op + (unsigned int)t * stride, s);
    }
#undef PREF
#undef LOADBLK
#undef COMPBLK
}

extern "C" void kernel_launch(void* const* d_in, const int* in_sizes, int n_in,
                              void* d_out, int out_size) {
    // metadata order: x_seq, v, a, decay_v, decay_a, threshold, beta, alpha
    const float* x      = (const float*)d_in[0];
    const float* v0     = (const float*)d_in[1];
    const float* a0     = (const float*)d_in[2];
    const float* dv_p   = (const float*)d_in[3];
    const float* da_p   = (const float*)d_in[4];
    const float* th_p   = (const float*)d_in[5];
    const float* beta_p = (const float*)d_in[6];
    // alpha (d_in[7]) only affects backward surrogate; unused in forward.

    int n_flat = in_sizes[1];
    int T      = in_sizes[0] / n_flat;

    float* out = (float*)d_out;

    int blocks = (n_flat + BLKN - 1) / BLKN;   // 1024 for n_flat=65536
    ALIF_24309514895931_kernel<<<blocks, BLKN>>>(
        x, v0, a0, dv_p, da_p, th_p, beta_p, out, n_flat, T);
}

// round 13
// speedup vs baseline: 1.0818x; 1.0818x over previous
#include <cuda_runtime.h>
#include <cstdint>

// ALIF forward scan — steady quad-buffered load pipeline + 32-line store bursts.
// x_seq: [T, n_flat] fp32; state v, a: [n_flat]; out spikes [T, n_flat] fp32.
// Per step: v = dv*v + x; th = th0 + beta*a; s = (v>th); v -= s*th; a = da*a + s.
//
// Thread-per-neuron, sequential T. Loads: 4-phase rotation of 8-element batches,
// consumed 3 batches (24 steps) after issue — steady ~24-32 lines in flight.
// Stores: outputs for 4 batches (32 steps) accumulate in registers, then burst
// as 32 consecutive STG lines. Coarse same-direction bursts reduce DRAM
// read/write turnaround, the suspected residual vs pure-stream bandwidth.

#define U 8       // timesteps per batch
#define BLKN 64   // threads per CTA

__device__ __forceinline__ float alif_step(float& v, float& a, float xv,
                                           float dv, float da, float th0, float beta) {
    v = fmaf(dv, v, xv);
    float th = fmaf(beta, a, th0);
    float s = (v > th) ? 1.0f : 0.0f;
    v = fmaf(-s, th, v);
    a = fmaf(da, a, s);
    return s;
}

__global__ __launch_bounds__(BLKN)
void ALIF_24309514895931_kernel(const float* __restrict__ x,
                                const float* __restrict__ v0,
                                const float* __restrict__ a0,
                                const float* __restrict__ dv_p,
                                const float* __restrict__ da_p,
                                const float* __restrict__ th_p,
                                const float* __restrict__ beta_p,
                                float* __restrict__ out,
                                int n_flat, int T) {
    int i = blockIdx.x * BLKN + threadIdx.x;
    if (i >= n_flat) return;

    const float dv   = *dv_p;
    const float da   = *da_p;
    const float th0  = *th_p;
    const float beta = *beta_p;

    float v = v0[i];
    float a = a0[i];

    const float* xp = x + i;
    float* op = out + i;
    const unsigned int stride = (unsigned int)n_flat;

    const int nb = T / U;

    float b0[U], b1[U], b2[U], b3[U];
    float st[4 * U];

#define LOADBLK(buf, bi)                                                    \
    {                                                                       \
        unsigned int base = (unsigned int)(bi) * U * stride;                \
        _Pragma("unroll")                                                   \
        for (int k = 0; k < U; k++)                                         \
            (buf)[k] = __ldcs(xp + base + (unsigned int)k * stride);        \
    }

    // Compute batch into the store buffer at slot offset (no stores yet).
#define COMPACC(buf, off)                                                   \
    {                                                                       \
        _Pragma("unroll")                                                   \
        for (int k = 0; k < U; k++)                                         \
            st[(off) + k] = alif_step(v, a, (buf)[k], dv, da, th0, beta);   \
    }

    // Compute batch with immediate stores (remainder path).
#define COMPSTORE(buf, bi)                                                  \
    {                                                                       \
        unsigned int base = (unsigned int)(bi) * U * stride;                \
        _Pragma("unroll")                                                   \
        for (int k = 0; k < U; k++) {                                       \
            float s = alif_step(v, a, (buf)[k], dv, da, th0, beta);         \
            __stcs(op + base + (unsigned int)k * stride, s);                \
        }                                                                   \
    }

    if (nb >= 4) {
        // Prologue: batches 0,1,2 in flight.
        LOADBLK(b0, 0);
        LOADBLK(b1, 1);
        LOADBLK(b2, 2);

        int g = 0;
        for (; g + 4 <= nb; g += 4) {
            if (g + 3 < nb) LOADBLK(b3, g + 3);
            COMPACC(b0, 0);
            if (g + 4 < nb) LOADBLK(b0, g + 4);
            COMPACC(b1, U);
            if (g + 5 < nb) LOADBLK(b1, g + 5);
            COMPACC(b2, 2 * U);
            if (g + 6 < nb) LOADBLK(b2, g + 6);
            COMPACC(b3, 3 * U);

            // Burst-store 32 lines for batches g..g+3.
            unsigned int base = (unsigned int)g * U * stride;
            #pragma unroll
            for (int j = 0; j < 4 * U; j++)
                __stcs(op + base + (unsigned int)j * stride, st[j]);
        }
        // Remainder (<4 batches): resident in b0,b1,b2 from guarded loads.
        int r = nb - g;
        if (r > 0) COMPSTORE(b0, g);
        if (r > 1) COMPSTORE(b1, g + 1);
        if (r > 2) COMPSTORE(b2, g + 2);
    } else {
        for (int b = 0; b < nb; b++) {
            LOADBLK(b0, b);
            COMPSTORE(b0, b);
        }
    }

    // Tail (T not a multiple of U).
    for (int t = nb * U; t < T; t++) {
        float xv = __ldcs(xp + (unsigned int)t * stride);
        float s = alif_step(v, a, xv, dv, da, th0, beta);
        __stcs(op + (unsigned int)t * stride, s);
    }
#undef LOADBLK
#undef COMPACC
#undef COMPSTORE
}

extern "C" void kernel_launch(void* const* d_in, const int* in_sizes, int n_in,
                              void* d_out, int out_size) {
    // metadata order: x_seq, v, a, decay_v, decay_a, threshold, beta, alpha
    const float* x      = (const float*)d_in[0];
    const float* v0     = (const float*)d_in[1];
    const float* a0     = (const float*)d_in[2];
    const float* dv_p   = (const float*)d_in[3];
    const float* da_p   = (const float*)d_in[4];
    const float* th_p   = (const float*)d_in[5];
    const float* beta_p = (const float*)d_in[6];
    // alpha (d_in[7]) only affects backward surrogate; unused in forward.

    int n_flat = in_sizes[1];
    int T      = in_sizes[0] / n_flat;

    float* out = (float*)d_out;

    int blocks = (n_flat + BLKN - 1) / BLKN;   // 1024 for n_flat=65536
    ALIF_24309514895931_kernel<<<blocks, BLKN>>>(
        x, v0, a0, dv_p, da_p, th_p, beta_p, out, n_flat, T);
}